// round 16
// baseline (speedup 1.0000x reference)
#include <cuda_runtime.h>
#include <cuda_bf16.h>
#include <cstddef>
#include <cstdint>

// ---------------- problem constants ----------------
#define BQ     4
#define DMODEL 1024
#define LSEQ   2048
#define DINNER 2048
#define DSTATE 16
#define DTRANK 64
#define BL     8192
#define XPN    96

// plane sizes (elements)
#define SZ_W1 ((size_t)4096 * 1024)
#define SZ_WX ((size_t)96 * 2048)
#define SZ_WD ((size_t)2048 * 64)
#define SZ_WOT ((size_t)2048 * 1024)   // Wo transposed
#define SZ_WP ((size_t)1024 * 1024)
#define SZ_WF ((size_t)1024 * 2048)    // fused Wp@Wo
#define SZ_XT ((size_t)BL * 1024)
#define SZ_UC ((size_t)BL * 2048)
#define SZ_XD ((size_t)BL * 96)
#define SZ_Y  ((size_t)BL * 2048)

// ---------------- scratch: hi plane at [0,N), lo plane at [N,2N) ----------------
__device__ __nv_bfloat16 g_w1b[2 * SZ_W1];
__device__ __nv_bfloat16 g_wxb[2 * SZ_WX];
__device__ __nv_bfloat16 g_wdb[2 * SZ_WD];
__device__ __nv_bfloat16 g_wotb[2 * SZ_WOT];
__device__ __nv_bfloat16 g_wpb[2 * SZ_WP];
__device__ __nv_bfloat16 g_wfb[2 * SZ_WF];
__device__ __nv_bfloat16 g_xTb[2 * SZ_XT];
__device__ __nv_bfloat16 g_ucb[2 * SZ_UC];
__device__ __nv_bfloat16 g_xdb[2 * SZ_XD];
__device__ __nv_bfloat16 g_yb [2 * SZ_Y];
__device__ __nv_bfloat16 g_dtb[2 * SZ_Y];        // delta planes (hi/lo, exact sum)
__device__ float g_xz   [(size_t)BL * 4096];     // u | silu(z)
__device__ float g_xdf  [(size_t)BL * 96];
__device__ float g_part [(size_t)8 * BL * XPN];  // split-K partials for x_proj

__device__ __forceinline__ float softplusf(float x) {
    return (x > 20.f) ? x : log1pf(__expf(x));
}
__device__ __forceinline__ float siluf(float x) {
    return x / (1.f + __expf(-x));
}
__device__ __forceinline__ uint32_t smem_u32(const void* p) {
    uint32_t a;
    asm("{ .reg .u64 t; cvta.to.shared.u64 t, %1; cvt.u32.u64 %0, t; }" : "=r"(a) : "l"(p));
    return a;
}

#define MMA_BF16(d, a, b0v, b1v) \
    asm volatile("mma.sync.aligned.m16n8k16.row.col.f32.bf16.bf16.f32 " \
        "{%0,%1,%2,%3}, {%4,%5,%6,%7}, {%8,%9}, {%0,%1,%2,%3};" \
        : "+f"((d)[0]), "+f"((d)[1]), "+f"((d)[2]), "+f"((d)[3]) \
        : "r"((a)[0]), "r"((a)[1]), "r"((a)[2]), "r"((a)[3]), "r"(b0v), "r"(b1v))

#define LDSM4(r, addr) \
    asm volatile("ldmatrix.sync.aligned.m8n8.x4.shared.b16 {%0,%1,%2,%3}, [%4];" \
        : "=r"((r)[0]), "=r"((r)[1]), "=r"((r)[2]), "=r"((r)[3]) : "r"(addr))

#define CP_ASYNC(dst, src) \
    asm volatile("cp.async.cg.shared.global [%0], [%1], 16;" :: "r"(dst), "l"(src) : "memory")
#define CP_ASYNC_Z(dst, src, sz) \
    asm volatile("cp.async.cg.shared.global [%0], [%1], 16, %2;" :: "r"(dst), "l"(src), "r"(sz) : "memory")
#define CP_COMMIT()  asm volatile("cp.async.commit_group;" ::: "memory")
#define CP_WAIT2()   asm volatile("cp.async.wait_group 2;" ::: "memory")
#define CP_WAIT1()   asm volatile("cp.async.wait_group 1;" ::: "memory")

// tile row: 64B, XOR swizzle on 16B chunks (conflict-free)
__device__ __forceinline__ uint32_t swz(int row, int cc) {
    uint32_t o = (uint32_t)(row * 64 + cc * 16);
    return o ^ ((((uint32_t)row >> 1) & 7u) << 4);
}

// stage layout: Ah[0,16K) Al[16K,32K) Bh[32K,40K) Bl[40K,48K)
#define STAGE_SZ 49152
#define NSTAGE   4
#define GEMM_SMEM (NSTAGE * STAGE_SZ)   // 196608

// ---------------- fp32 -> bf16 hi/lo converters ----------------
__device__ __forceinline__ void cvt_body(const float* __restrict__ s,
                                         __nv_bfloat16* __restrict__ d,
                                         size_t n, size_t i) {
    float4 v = *((const float4*)s + i);
    __nv_bfloat162 h0 = __floats2bfloat162_rn(v.x, v.y);
    __nv_bfloat162 h1 = __floats2bfloat162_rn(v.z, v.w);
    __nv_bfloat162 l0 = __floats2bfloat162_rn(v.x - __bfloat162float(h0.x),
                                              v.y - __bfloat162float(h0.y));
    __nv_bfloat162 l1 = __floats2bfloat162_rn(v.z - __bfloat162float(h1.x),
                                              v.w - __bfloat162float(h1.y));
    ((__nv_bfloat162*)d)[2 * i]     = h0;
    ((__nv_bfloat162*)d)[2 * i + 1] = h1;
    ((__nv_bfloat162*)(d + n))[2 * i]     = l0;
    ((__nv_bfloat162*)(d + n))[2 * i + 1] = l1;
}

__global__ void cvt_k(const float* __restrict__ src, __nv_bfloat16* __restrict__ db, size_t n) {
    size_t i = (size_t)blockIdx.x * 256 + threadIdx.x;
    cvt_body(src, db, n, i);
}

__global__ void cvt_rest(const float* s0, __nv_bfloat16* d0, size_t n0,
                         const float* s1, __nv_bfloat16* d1, size_t n1,
                         const float* s2, __nv_bfloat16* d2, size_t n2) {
    size_t j = (size_t)blockIdx.x * 256 + threadIdx.x;
    if (j < n0 / 4) { cvt_body(s0, d0, n0, j); return; }
    j -= n0 / 4;
    if (j < n1 / 4) { cvt_body(s1, d1, n1, j); return; }
    j -= n1 / 4;
    if (j < n2 / 4) { cvt_body(s2, d2, n2, j); return; }
}

// ---------------- x transpose -> hi/lo planes ----------------
__global__ void transpose_k(const float* __restrict__ x) {
    __shared__ float t[32][33];
    int b = blockIdx.z;
    int l0 = blockIdx.x * 32, k0 = blockIdx.y * 32;
    int tx = threadIdx.x, ty = threadIdx.y;
#pragma unroll
    for (int i = 0; i < 4; i++)
        t[ty + 8 * i][tx] = x[((size_t)(b * DMODEL + k0 + ty + 8 * i)) * LSEQ + l0 + tx];
    __syncthreads();
#pragma unroll
    for (int i = 0; i < 4; i++) {
        float v = t[tx][ty + 8 * i];
        size_t o = ((size_t)(b * LSEQ + l0 + ty + 8 * i)) * DMODEL + k0 + tx;
        __nv_bfloat16 h = __float2bfloat16(v);
        g_xTb[o] = h;
        g_xTb[SZ_XT + o] = __float2bfloat16(v - __bfloat162float(h));
    }
}

// ---------------- Wo transpose: (1024 x 2048) -> woT planes (2048 x 1024) ----------------
__global__ void txp_wo(const float* __restrict__ src) {
    __shared__ float t[32][33];
    int c0 = blockIdx.x * 32, r0 = blockIdx.y * 32;
    int tx = threadIdx.x, ty = threadIdx.y;
#pragma unroll
    for (int i = 0; i < 4; i++)
        t[ty + 8 * i][tx] = src[(size_t)(r0 + ty + 8 * i) * 2048 + c0 + tx];
    __syncthreads();
#pragma unroll
    for (int i = 0; i < 4; i++) {
        float v = t[tx][ty + 8 * i];
        size_t o = (size_t)(c0 + ty + 8 * i) * 1024 + r0 + tx;
        __nv_bfloat16 h = __float2bfloat16(v);
        g_wotb[o] = h;
        g_wotb[SZ_WOT + o] = __float2bfloat16(v - __bfloat162float(h));
    }
}

// ---------------- bf16x3 GEMM: 512 threads, 16 warps (4x4), block 256x128, warp 64x32 ----------------
// EPI: 0 fp32 (+split-K offset via blockIdx.z) | 2 transposed+bias
//      4 hi/lo only | 5 fp32, silu applied for cn >= DINNER | 6 softplus+bias -> hi/lo planes
template<int EPI>
__global__ void __launch_bounds__(512, 1)
hgemm(const __nv_bfloat16* __restrict__ Ah, const __nv_bfloat16* __restrict__ Al,
      const __nv_bfloat16* __restrict__ Bh, const __nv_bfloat16* __restrict__ Bl,
      const float* __restrict__ bias, float* __restrict__ C,
      __nv_bfloat16* __restrict__ Ch, __nv_bfloat16* __restrict__ Cl,
      int M, int N, int K, int lda, int ldc)
{
    extern __shared__ char smem[];
    const uint32_t sb = smem_u32(smem);
    const int tid = threadIdx.x, lane = tid & 31, wid = tid >> 5;
    const int wm = wid >> 2, wn = wid & 3;       // 4 x 4 warp grid (rows x cols)
    const int bm = blockIdx.y * 256, bn = blockIdx.x * 128;
    const int kw = K / gridDim.z;                // split-K window
    const int kb = blockIdx.z * kw;
    const int nc = kw >> 5;

    const uint32_t akh = (uint32_t)(lane >> 4) << 4;
    uint32_t ab[4];
#pragma unroll
    for (int i = 0; i < 4; i++)
        ab[i] = swz(wm * 64 + i * 16 + (lane & 15), 0) ^ akh;
    const int brl = wn * 32 + (lane & 15);
    const uint32_t bb0 = swz(brl, 0) ^ akh;
    const uint32_t bb1 = swz(brl + 16, 0) ^ akh;

    float acc[4][4][4];
#pragma unroll
    for (int i = 0; i < 4; i++)
#pragma unroll
        for (int j = 0; j < 4; j++)
#pragma unroll
            for (int t = 0; t < 4; t++) acc[i][j][t] = 0.f;

    // ---- persistent loader state ----
    const int rq = tid >> 2;                     // 0..127
    const int cc = tid & 3;
    const uint32_t sA0 = swz(rq, cc);
    const uint32_t sA1 = swz(128 + rq, cc);
    const uint32_t sBo = swz(rq, cc);
    const int nB = bn + rq;
    const uint32_t okz = (nB < N) ? 16u : 0u;
    const __nv_bfloat16* pA0h = Ah + (size_t)(bm + rq) * lda + kb + cc * 8;
    const __nv_bfloat16* pA1h = Ah + (size_t)(bm + 128 + rq) * lda + kb + cc * 8;
    const __nv_bfloat16* pA0l = Al + (size_t)(bm + rq) * lda + kb + cc * 8;
    const __nv_bfloat16* pA1l = Al + (size_t)(bm + 128 + rq) * lda + kb + cc * 8;
    const __nv_bfloat16* pBh  = Bh + (size_t)(nB < N ? nB : 0) * K + kb + cc * 8;
    const __nv_bfloat16* pBl  = Bl + (size_t)(nB < N ? nB : 0) * K + kb + cc * 8;

    auto issue = [&](int s) {
        const uint32_t st = sb + s * STAGE_SZ;
        CP_ASYNC(st + sA0, pA0h);
        CP_ASYNC(st + sA1, pA1h);
        CP_ASYNC(st + 16384 + sA0, pA0l);
        CP_ASYNC(st + 16384 + sA1, pA1l);
        CP_ASYNC_Z(st + 32768 + sBo, pBh, okz);
        CP_ASYNC_Z(st + 40960 + sBo, pBl, okz);
        pA0h += 32; pA1h += 32; pA0l += 32; pA1l += 32;
        pBh  += 32; pBl  += 32;
    };

    issue(0); CP_COMMIT();
    if (nc > 1) issue(1);
    CP_COMMIT();
    if (nc > 2) issue(2);
    CP_COMMIT();

    for (int c = 0; c < nc; c++) {
        CP_WAIT2();
        __syncthreads();
        if (c + 3 < nc) issue((c + 3) & (NSTAGE - 1));
        CP_COMMIT();

        const uint32_t st = sb + (c & (NSTAGE - 1)) * STAGE_SZ;
#pragma unroll
        for (int ks = 0; ks < 2; ks++) {
            const uint32_t kx = (uint32_t)ks << 5;
            uint32_t ah[4][4], bh[2][4];
#pragma unroll
            for (int i = 0; i < 4; i++) LDSM4(ah[i], st + (ab[i] ^ kx));
            LDSM4(bh[0], st + 32768 + (bb0 ^ kx));
            LDSM4(bh[1], st + 32768 + (bb1 ^ kx));
#pragma unroll
            for (int i = 0; i < 4; i++) {
                MMA_BF16(acc[i][0], ah[i], bh[0][0], bh[0][2]);
                MMA_BF16(acc[i][1], ah[i], bh[0][1], bh[0][3]);
                MMA_BF16(acc[i][2], ah[i], bh[1][0], bh[1][2]);
                MMA_BF16(acc[i][3], ah[i], bh[1][1], bh[1][3]);
            }
            {
                uint32_t bl[2][4];
                LDSM4(bl[0], st + 40960 + (bb0 ^ kx));
                LDSM4(bl[1], st + 40960 + (bb1 ^ kx));
#pragma unroll
                for (int i = 0; i < 4; i++) {
                    MMA_BF16(acc[i][0], ah[i], bl[0][0], bl[0][2]);
                    MMA_BF16(acc[i][1], ah[i], bl[0][1], bl[0][3]);
                    MMA_BF16(acc[i][2], ah[i], bl[1][0], bl[1][2]);
                    MMA_BF16(acc[i][3], ah[i], bl[1][1], bl[1][3]);
                }
            }
            {
                uint32_t al[4][4];
#pragma unroll
                for (int i = 0; i < 4; i++) LDSM4(al[i], st + 16384 + (ab[i] ^ kx));
#pragma unroll
                for (int i = 0; i < 4; i++) {
                    MMA_BF16(acc[i][0], al[i], bh[0][0], bh[0][2]);
                    MMA_BF16(acc[i][1], al[i], bh[0][1], bh[0][3]);
                    MMA_BF16(acc[i][2], al[i], bh[1][0], bh[1][2]);
                    MMA_BF16(acc[i][3], al[i], bh[1][1], bh[1][3]);
                }
            }
        }
        __syncthreads();
    }

    // ---------------- epilogue ----------------
    const int lr = lane >> 2, lc = lane & 3;
#pragma unroll
    for (int i = 0; i < 4; i++) {
#pragma unroll
        for (int j = 0; j < 4; j++) {
            int r0 = bm + wm * 64 + i * 16 + lr;
            int cn = bn + wn * 32 + j * 8 + lc * 2;
            if (cn >= N) continue;
            float c0 = acc[i][j][0], c1 = acc[i][j][1];
            float c2 = acc[i][j][2], c3 = acc[i][j][3];
            if (EPI == 0) {
                float* Cz = C + (size_t)blockIdx.z * (size_t)M * ldc;
                *(float2*)&Cz[(size_t)r0 * ldc + cn]       = make_float2(c0, c1);
                *(float2*)&Cz[(size_t)(r0 + 8) * ldc + cn] = make_float2(c2, c3);
            } else if (EPI == 5) {
                if (cn >= DINNER) {
                    c0 = siluf(c0); c1 = siluf(c1);
                    c2 = siluf(c2); c3 = siluf(c3);
                }
                *(float2*)&C[(size_t)r0 * ldc + cn]       = make_float2(c0, c1);
                *(float2*)&C[(size_t)(r0 + 8) * ldc + cn] = make_float2(c2, c3);
            } else if (EPI == 2) {
                float b0 = bias[cn], b1 = bias[cn + 1];
                int bb = r0 >> 11, l0 = r0 & (LSEQ - 1);
                size_t base0 = ((size_t)(bb * DMODEL + cn)) * LSEQ;
                C[base0 + l0]            = c0 + b0;
                C[base0 + LSEQ + l0]     = c1 + b1;
                C[base0 + l0 + 8]        = c2 + b0;
                C[base0 + LSEQ + l0 + 8] = c3 + b1;
            } else { // EPI 4 / 6: hi/lo planes (EPI 6 applies softplus+bias first)
                if (EPI == 6) {
                    float b0 = bias[cn], b1 = bias[cn + 1];
                    c0 = softplusf(c0 + b0); c1 = softplusf(c1 + b1);
                    c2 = softplusf(c2 + b0); c3 = softplusf(c3 + b1);
                }
                __nv_bfloat162 h0 = __floats2bfloat162_rn(c0, c1);
                __nv_bfloat162 h1 = __floats2bfloat162_rn(c2, c3);
                __nv_bfloat162 l0v = __floats2bfloat162_rn(c0 - __bfloat162float(h0.x),
                                                           c1 - __bfloat162float(h0.y));
                __nv_bfloat162 l1v = __floats2bfloat162_rn(c2 - __bfloat162float(h1.x),
                                                           c3 - __bfloat162float(h1.y));
                *(__nv_bfloat162*)&Ch[(size_t)r0 * ldc + cn]       = h0;
                *(__nv_bfloat162*)&Ch[(size_t)(r0 + 8) * ldc + cn] = h1;
                *(__nv_bfloat162*)&Cl[(size_t)r0 * ldc + cn]       = l0v;
                *(__nv_bfloat162*)&Cl[(size_t)(r0 + 8) * ldc + cn] = l1v;
            }
        }
    }
}

// ---------------- split-K reduce for x_proj (8 partials) + hi/lo plane emit ----------------
__global__ void reduce_x() {
    size_t i = (size_t)blockIdx.x * 256 + threadIdx.x;   // < BL*XPN
    const size_t S = (size_t)BL * XPN;
    float s = 0.f;
#pragma unroll
    for (int p = 0; p < 8; p++) s += g_part[i + (size_t)p * S];
    g_xdf[i] = s;
    __nv_bfloat16 h = __float2bfloat16(s);
    g_xdb[i] = h;
    g_xdb[SZ_XD + i] = __float2bfloat16(s - __bfloat162float(h));
}

// ---------------- depthwise causal conv + SiLU -> planes only ----------------
__global__ void conv_silu_k(const float* __restrict__ cw, const float* __restrict__ cb) {
    int e = blockIdx.x * 256 + threadIdx.x;
    int b = blockIdx.z;
    int l0 = blockIdx.y * 128;
    float w0 = cw[e * 4], w1 = cw[e * 4 + 1], w2 = cw[e * 4 + 2], w3 = cw[e * 4 + 3];
    float bias = cb[e];
    size_t base = (size_t)b * LSEQ * 4096 + e;
    float u0 = (l0 >= 3) ? g_xz[base + (size_t)(l0 - 3) * 4096] : 0.f;
    float u1 = (l0 >= 2) ? g_xz[base + (size_t)(l0 - 2) * 4096] : 0.f;
    float u2 = (l0 >= 1) ? g_xz[base + (size_t)(l0 - 1) * 4096] : 0.f;
    for (int l = l0; l < l0 + 128; l++) {
        float u3 = g_xz[base + (size_t)l * 4096];
        float v = fmaf(w0, u0, fmaf(w1, u1, fmaf(w2, u2, fmaf(w3, u3, bias))));
        float s = siluf(v);
        size_t o = (size_t)(b * LSEQ + l) * DINNER + e;
        __nv_bfloat16 h = __float2bfloat16(s);
        g_ucb[o] = h;
        g_ucb[SZ_UC + o] = __float2bfloat16(s - __bfloat162float(h));   // exact: s = hi+lo
        u0 = u1; u1 = u2; u2 = u3;
    }
}

// ---------------- selective scan: SMEM-staged, 32 ch/block, 128 thr, 2 CTAs/SM ----------------
// stage bytes: dh[0,4K) dl[4K,8K) uh[8K,12K) ul[12K,16K) z[16K,24K) BC[24K,32K)
#define SC_T 64
#define SC_STB 32768
#define SCAN_SMEM (2 * SC_STB)   // 65536

__global__ void __launch_bounds__(128, 2)
scan_k(const float* __restrict__ A_log, const float* __restrict__ Dv) {
    extern __shared__ char ssm[];
    const int tid = threadIdx.x;
    const int ch  = tid >> 2;                    // 0..31
    const int chB = blockIdx.x * 32;
    const int g   = chB + ch;
    const int b   = chB >> 11, d = g & (DINNER - 1);
    const int d0  = chB & (DINNER - 1);
    const int nb  = (tid & 3) * 4;
    const size_t rowbase = (size_t)b * LSEQ;
    const bool wr = ((tid & 3) == 0);

    float4 al4 = *(const float4*)&A_log[d * DSTATE + nb];
    const float Ac0 = -__expf(al4.x), Ac1 = -__expf(al4.y);
    const float Ac2 = -__expf(al4.z), Ac3 = -__expf(al4.w);
    const float Dd = Dv[d];
    float h0 = 0.f, h1 = 0.f, h2 = 0.f, h3 = 0.f;

    const uint32_t sbase = smem_u32(ssm);
    const __nv_bfloat16* PLd = g_dtb;                  // delta planes
    const __nv_bfloat16* PLu = g_ucb;                  // u planes

    auto stage_load = [&](int tile, int s) {
        const uint32_t st = sbase + (uint32_t)s * SC_STB;
        const int row0 = tile * SC_T;
        // 4 bf16 plane regions: 256 chunks each (64 rows x 4 chunks)
#pragma unroll
        for (int i = 0; i < 8; i++) {
            int q   = tid + i * 128;
            int reg = q >> 8;                    // 0..3
            int t   = (q >> 2) & 63;
            int c4  = q & 3;
            size_t r = rowbase + row0 + t;
            uint32_t so = st + (uint32_t)reg * 4096 + (uint32_t)(t * 64 + c4 * 16);
            const __nv_bfloat16* src =
                (reg == 0) ? PLd + r * DINNER + d0 + c4 * 8 :
                (reg == 1) ? PLd + SZ_Y + r * DINNER + d0 + c4 * 8 :
                (reg == 2) ? PLu + r * DINNER + d0 + c4 * 8 :
                             PLu + SZ_UC + r * DINNER + d0 + c4 * 8;
            CP_ASYNC(so, src);
        }
        // z fp32: 512 chunks (64 rows x 8)
#pragma unroll
        for (int i = 0; i < 4; i++) {
            int q  = tid + i * 128;
            int t  = q >> 3;
            int c4 = q & 7;
            size_t r = rowbase + row0 + t;
            CP_ASYNC(st + 16384 + (uint32_t)(t * 128 + c4 * 16),
                     g_xz + r * 4096 + DINNER + d0 + c4 * 4);
        }
        // BC fp32: 512 chunks (64 rows x 8)
#pragma unroll
        for (int i = 0; i < 4; i++) {
            int q  = tid + i * 128;
            int t  = q >> 3;
            int c4 = q & 7;
            size_t r = rowbase + row0 + t;
            CP_ASYNC(st + 24576 + (uint32_t)(t * 128 + c4 * 16),
                     g_xdf + r * XPN + DTRANK + c4 * 4);
        }
    };

    stage_load(0, 0); CP_COMMIT();
    stage_load(1, 1); CP_COMMIT();

    const int NT = LSEQ / SC_T;
    for (int tile = 0; tile < NT; tile++) {
        CP_WAIT1();
        __syncthreads();
        const char* st = ssm + (tile & 1) * SC_STB;
        const __nv_bfloat16* dh = (const __nv_bfloat16*)st;
        const __nv_bfloat16* dl = dh + 2048;
        const __nv_bfloat16* uh = (const __nv_bfloat16*)(st + 8192);
        const __nv_bfloat16* ul = uh + 2048;
        const float* zz = (const float*)(st + 16384);
        const float* bc = (const float*)(st + 24576);
        const size_t rb = rowbase + (size_t)tile * SC_T;
#pragma unroll 4
        for (int t = 0; t < SC_T; t++) {
            float dval = __bfloat162float(dh[t * 32 + ch]) + __bfloat162float(dl[t * 32 + ch]);
            float uval = __bfloat162float(uh[t * 32 + ch]) + __bfloat162float(ul[t * 32 + ch]);
            float4 Bv = *(const float4*)&bc[t * 32 + nb];
            float4 Cv = *(const float4*)&bc[t * 32 + 16 + nb];
            float dBu = dval * uval;
            h0 = fmaf(__expf(dval * Ac0), h0, dBu * Bv.x);
            h1 = fmaf(__expf(dval * Ac1), h1, dBu * Bv.y);
            h2 = fmaf(__expf(dval * Ac2), h2, dBu * Bv.z);
            h3 = fmaf(__expf(dval * Ac3), h3, dBu * Bv.w);
            float p = fmaf(h0, Cv.x, fmaf(h1, Cv.y, fmaf(h2, Cv.z, h3 * Cv.w)));
            p += __shfl_xor_sync(0xffffffffu, p, 1);
            p += __shfl_xor_sync(0xffffffffu, p, 2);
            if (wr) {
                float zs = zz[t * 32 + ch];
                float yv = (p + uval * Dd) * zs;
                size_t r = rb + t;
                __nv_bfloat16 hh = __float2bfloat16(yv);
                g_yb[r * DINNER + d] = hh;
                g_yb[SZ_Y + r * DINNER + d] = __float2bfloat16(yv - __bfloat162float(hh));
            }
        }
        __syncthreads();
        if (tile + 2 < NT) stage_load(tile + 2, tile & 1);
        CP_COMMIT();
    }
}

// ---------------- launch ----------------
extern "C" void kernel_launch(void* const* d_in, const int* in_sizes, int n_in,
                              void* d_out, int out_size)
{
    const float* x          = (const float*)d_in[0];
    const float* in_proj_w  = (const float*)d_in[1];
    const float* conv_w     = (const float*)d_in[2];
    const float* conv_b     = (const float*)d_in[3];
    const float* x_proj_w   = (const float*)d_in[4];
    const float* dt_proj_w  = (const float*)d_in[5];
    const float* dt_proj_b  = (const float*)d_in[6];
    const float* A_log      = (const float*)d_in[7];
    const float* Dv         = (const float*)d_in[8];
    const float* out_proj_w = (const float*)d_in[9];
    const float* proj_w     = (const float*)d_in[10];
    const float* proj_b     = (const float*)d_in[11];
    float* out = (float*)d_out;

    __nv_bfloat16 *w1b, *wxb, *wdb, *wotb, *wpb, *wfb, *xTb, *ucb, *xdb, *yb, *dtb;
    float *xz, *xdf, *part;
    cudaGetSymbolAddress((void**)&w1b,  g_w1b);
    cudaGetSymbolAddress((void**)&wxb,  g_wxb);
    cudaGetSymbolAddress((void**)&wdb,  g_wdb);
    cudaGetSymbolAddress((void**)&wotb, g_wotb);
    cudaGetSymbolAddress((void**)&wpb,  g_wpb);
    cudaGetSymbolAddress((void**)&wfb,  g_wfb);
    cudaGetSymbolAddress((void**)&xTb,  g_xTb);
    cudaGetSymbolAddress((void**)&ucb,  g_ucb);
    cudaGetSymbolAddress((void**)&xdb,  g_xdb);
    cudaGetSymbolAddress((void**)&yb,   g_yb);
    cudaGetSymbolAddress((void**)&dtb,  g_dtb);
    cudaGetSymbolAddress((void**)&xz,    g_xz);
    cudaGetSymbolAddress((void**)&xdf,   g_xdf);
    cudaGetSymbolAddress((void**)&part,  g_part);

    cudaFuncSetAttribute(hgemm<0>, cudaFuncAttributeMaxDynamicSharedMemorySize, GEMM_SMEM);
    cudaFuncSetAttribute(hgemm<2>, cudaFuncAttributeMaxDynamicSharedMemorySize, GEMM_SMEM);
    cudaFuncSetAttribute(hgemm<4>, cudaFuncAttributeMaxDynamicSharedMemorySize, GEMM_SMEM);
    cudaFuncSetAttribute(hgemm<5>, cudaFuncAttributeMaxDynamicSharedMemorySize, GEMM_SMEM);
    cudaFuncSetAttribute(hgemm<6>, cudaFuncAttributeMaxDynamicSharedMemorySize, GEMM_SMEM);
    cudaFuncSetAttribute(scan_k,   cudaFuncAttributeMaxDynamicSharedMemorySize, SCAN_SMEM);

    // [0] in_proj weight conversion
    cvt_k<<<(int)(SZ_W1 / 1024), 256>>>(in_proj_w, w1b, SZ_W1);
    // [1] remaining weight conversions (wx, wd, wp)
    {
        size_t tot4 = (SZ_WX + SZ_WD + SZ_WP) / 4;
        cvt_rest<<<(int)((tot4 + 255) / 256), 256>>>(
            x_proj_w, wxb, SZ_WX, dt_proj_w, wdb, SZ_WD, proj_w, wpb, SZ_WP);
    }
    // [2] x transpose
    transpose_k<<<dim3(LSEQ / 32, DMODEL / 32, BQ), dim3(32, 8)>>>(x);
    // [3] in_proj: xz = xT @ W1^T (silu on z half)  <-- profiled slot
    hgemm<5><<<dim3(32, 32), 512, GEMM_SMEM>>>(xTb, xTb + SZ_XT, w1b, w1b + SZ_W1,
        nullptr, xz, nullptr, nullptr, BL, 4096, DMODEL, DMODEL, 4096);
    // [4] Wo transpose -> woT planes
    txp_wo<<<dim3(2048 / 32, 1024 / 32), dim3(32, 8)>>>(out_proj_w);
    // [5] Wf = Wp @ Wo  (1024 x 2048, K=1024) -> planes
    hgemm<4><<<dim3(16, 4), 512, GEMM_SMEM>>>(wpb, wpb + SZ_WP, wotb, wotb + SZ_WOT,
        nullptr, nullptr, wfb, wfb + SZ_WF, 1024, 2048, 1024, 1024, 2048);
    // [6] conv + silu -> u planes
    conv_silu_k<<<dim3(DINNER / 256, LSEQ / 128, BQ), 256>>>(conv_w, conv_b);
    // [7] x_proj split-K=8 -> partials
    hgemm<0><<<dim3(1, 32, 8), 512, GEMM_SMEM>>>(ucb, ucb + SZ_UC, wxb, wxb + SZ_WX,
        nullptr, part, nullptr, nullptr, BL, XPN, DINNER, DINNER, XPN);
    // [8] reduce partials -> xdf + planes
    reduce_x<<<(int)((size_t)BL * XPN / 256), 256>>>();
    // [9] delta = softplus(dt_low @ Wd^T + b) -> planes
    hgemm<6><<<dim3(16, 32), 512, GEMM_SMEM>>>(xdb, xdb + SZ_XD, wdb, wdb + SZ_WD,
        dt_proj_b, nullptr, dtb, dtb + SZ_Y, BL, DINNER, DTRANK, XPN, DINNER);
    // [10] selective scan -> y planes (SMEM-staged, 2 CTAs/SM)
    scan_k<<<BL / 32, 128, SCAN_SMEM>>>(A_log, Dv);
    // [11] out = (y @ Wf^T + b), transposed store — fused out_proj+proj
    hgemm<2><<<dim3(8, 32), 512, GEMM_SMEM>>>(yb, yb + SZ_Y, wfb, wfb + SZ_WF,
        proj_b, out, nullptr, nullptr, BL, DMODEL, DINNER, DINNER, 0);
}